// round 15
// baseline (speedup 1.0000x reference)
#include <cuda_runtime.h>
#include <cuda_fp16.h>
#include <math.h>

typedef unsigned int u32;
typedef __half hf;

#define SS 1024
#define HH 16
#define HDD 64
#define NBH 32

// ---------------- scratch (device globals) ----------------
__device__ hf g_x[2048*1024];
__device__ hf g_w[3*1024*1024];
__device__ hf g_de[2047*64];
__device__ hf g_q[NBH*SS*HDD];
__device__ hf g_k[NBH*SS*HDD];
__device__ hf g_v[NBH*SS*HDD];
__device__ hf g_sc[(size_t)NBH*SS*SS];

// ---------------- helpers ----------------
__device__ __forceinline__ u32 sptr(const void* p){ return (u32)__cvta_generic_to_shared(p); }
__device__ __forceinline__ void ldsm4(u32& r0,u32& r1,u32& r2,u32& r3,u32 a){
    asm volatile("ldmatrix.sync.aligned.m8n8.x4.shared.b16 {%0,%1,%2,%3},[%4];"
                 :"=r"(r0),"=r"(r1),"=r"(r2),"=r"(r3):"r"(a));
}
__device__ __forceinline__ void ldsm4t(u32& r0,u32& r1,u32& r2,u32& r3,u32 a){
    asm volatile("ldmatrix.sync.aligned.m8n8.x4.trans.shared.b16 {%0,%1,%2,%3},[%4];"
                 :"=r"(r0),"=r"(r1),"=r"(r2),"=r"(r3):"r"(a));
}
__device__ __forceinline__ void mma16816(float (&c)[4], const u32 (&a)[4], u32 b0, u32 b1){
    asm volatile("mma.sync.aligned.m16n8k16.row.col.f32.f16.f16.f32 "
                 "{%0,%1,%2,%3},{%4,%5,%6,%7},{%8,%9},{%0,%1,%2,%3};"
                 :"+f"(c[0]),"+f"(c[1]),"+f"(c[2]),"+f"(c[3])
                 :"r"(a[0]),"r"(a[1]),"r"(a[2]),"r"(a[3]),"r"(b0),"r"(b1));
}
__device__ __forceinline__ u32 pack2h(float a, float b){
    __half2 t; t.x=__float2half_rn(a); t.y=__float2half_rn(b);
    return *(u32*)&t;
}

#define CP16(dst, src) \
    asm volatile("cp.async.cg.shared.global [%0], [%1], 16;" :: "r"(dst), "l"(src))
#define CP_COMMIT() asm volatile("cp.async.commit_group;" ::: "memory")
#define CP_WAIT(n)  asm volatile("cp.async.wait_group %0;" :: "n"(n) : "memory")

// ============================================================================
// K0: fp32 -> fp16 (single rounding) for X, W, de.
// ============================================================================
__global__ __launch_bounds__(256)
void cvt_kernel(const float* __restrict__ X, const float* __restrict__ Wq,
                const float* __restrict__ Wk, const float* __restrict__ Wv,
                const float* __restrict__ de)
{
    int i = blockIdx.x * 256 + threadIdx.x;
    if (i >= 1343472) return;
    const float* src; hf* dst; int off;
    if (i < 524288) {
        src = X; dst = g_x; off = i;
    } else if (i < 1310720) {
        off = i - 524288;
        int wsel = off >> 18;
        src = (wsel==0)?Wq:(wsel==1)?Wk:Wv;
        dst = g_w + (size_t)wsel * 1048576;
        off &= 262143;
    } else {
        off = i - 1310720; src = de; dst = g_de;
    }
    float4 v = *(const float4*)(src + (size_t)off * 4);
    *(uint2*)(dst + (size_t)off*4) = make_uint2(pack2h(v.x,v.y), pack2h(v.z,v.w));
}

// ============================================================================
// K1: q/k/v = X @ W^T + b (fp16 x1). CTA 128x128, BK=64, cp.async 2-stage,
// 2 CTAs/SM.
// ============================================================================
#define QKV_SMEM (2*36864)
__global__ __launch_bounds__(256, 2)
void qkv_mma(const float* __restrict__ bq, const float* __restrict__ bk,
             const float* __restrict__ bv)
{
    extern __shared__ __align__(16) char smem[];
    const u32 sb = sptr(smem);

    const int tid = threadIdx.x, wid = tid>>5, lane = tid&31;
    const int warpM = wid>>2, warpN = wid&3;
    const int z = blockIdx.z, n0 = blockIdx.x*128, m0 = blockIdx.y*128;
    const int lr = lane&15, lc8 = (lane>>4)*8, g = lane>>2, t = lane&3;

    const hf* B = g_w + (size_t)z*1048576;
    const float* bias = (z==0)?bq:(z==1)?bk:bv;
    hf* dq = (z==0)?g_q:(z==1)?g_k:g_v;

    float acc[4][4][4];
#pragma unroll
    for (int i=0;i<4;i++)
#pragma unroll
        for (int j=0;j<4;j++)
#pragma unroll
            for (int c=0;c<4;c++) acc[i][j][c]=0.f;

    auto load_stage = [&](int st, int k0){
        const u32 base = sb + st*36864;
#pragma unroll
        for (int rep=0;rep<8;rep++){
            int idx = rep*256 + tid;
            int mat = idx >> 10, rem = idx & 1023;
            int row = rem >> 3, s8 = rem & 7;
            u32 dst = base + mat*18432 + row*144 + s8*16;
            const hf* srcp =
                (mat==0) ? &g_x[(size_t)(m0+row)*1024 + k0 + s8*8]
                         : &B[(size_t)(n0+row)*1024 + k0 + s8*8];
            CP16(dst, srcp);
        }
    };

    load_stage(0, 0); CP_COMMIT();

    for (int c = 0; c < 16; c++) {
        if (c < 15) { load_stage((c+1)&1, (c+1)*64); CP_COMMIT(); CP_WAIT(1); }
        else        { CP_WAIT(0); }
        __syncthreads();
        const u32 st = sb + (c&1)*36864;
#pragma unroll
        for (int kb=0;kb<64;kb+=16){
            u32 ah[4][4], bb[4][2];
#pragma unroll
            for (int mt=0;mt<4;mt++){
                u32 ra = st + ((warpM*64+mt*16+lr)*72 + kb + lc8)*2;
                ldsm4(ah[mt][0],ah[mt][1],ah[mt][2],ah[mt][3], ra);
            }
#pragma unroll
            for (int gg=0;gg<2;gg++){
                u32 rb = st + 18432 + ((warpN*32+gg*16+lr)*72 + kb + lc8)*2;
                u32 r0,r1,r2,r3;
                ldsm4(r0,r1,r2,r3, rb);
                bb[2*gg][0]=r0; bb[2*gg][1]=r2; bb[2*gg+1][0]=r1; bb[2*gg+1][1]=r3;
            }
#pragma unroll
            for (int mt=0;mt<4;mt++)
#pragma unroll
                for (int nt=0;nt<4;nt++)
                    mma16816(acc[mt][nt], ah[mt], bb[nt][0], bb[nt][1]);
        }
        __syncthreads();
    }

#pragma unroll
    for (int mt=0;mt<4;mt++)
#pragma unroll
        for (int nt=0;nt<4;nt++){
            int ncol = n0 + warpN*32 + nt*8 + 2*t;
            float b0 = bias[ncol], b1 = bias[ncol+1];
            int h = ncol>>6, dd = ncol&63;
#pragma unroll
            for (int rr=0;rr<2;rr++){
                int m = m0 + warpM*64 + mt*16 + g + rr*8;
                int b_ = m>>10, l = m&1023;
                float v0 = acc[mt][nt][rr*2+0] + b0;
                float v1 = acc[mt][nt][rr*2+1] + b1;
                size_t o = (((size_t)(b_*HH + h))*SS + l)*HDD + dd;
                *(u32*)&dq[o] = pack2h(v0, v1);
            }
        }
}

// ============================================================================
// K2: scores = (q k^T)[fp16 x1] + Toeplitz(Q DE^T)[x1], *0.125 + mask -> fp16
// ============================================================================
#define SC_SMEM 61440
#define SC_Q  0
#define SC_K  18432
#define SC_T  18432
#define SC_DE 52224
__global__ __launch_bounds__(256, 2)
void scores_mma(const float* __restrict__ mask)
{
    extern __shared__ __align__(16) char smem[];
    const u32 sb = sptr(smem);
    float* sT = (float*)(smem + SC_T);

    const int tid = threadIdx.x, wid = tid>>5, lane = tid&31;
    const int warpM = wid>>2, warpN = wid&3;
    const int bh = blockIdx.z, l0 = blockIdx.y*128, r0 = blockIdx.x*128;
    const int b_ = bh>>4;
    const int jb = l0 - r0 + 896;
    const int lr = lane&15, lc8 = (lane>>4)*8, g = lane>>2, t = lane&3;

    const hf* qq = g_q + (size_t)bh*SS*HDD;
    const hf* kk = g_k + (size_t)bh*SS*HDD;

    auto load_de = [&](int cchunk){
#pragma unroll
        for (int rep=0;rep<2;rep++){
            int idx = rep*256 + tid;
            int row = idx >> 3, s8 = idx & 7;
            int der = jb + cchunk*64 + row; if (der > 2046) der = 2046;
            CP16(sb + SC_DE + row*144 + s8*16, &g_de[(size_t)der*64 + s8*8]);
        }
    };

#pragma unroll
    for (int rep=0;rep<8;rep++){
        int idx = rep*256 + tid;
        int mat = idx >> 10, rem = idx & 1023;
        int row = rem >> 3, s8 = rem & 7;
        u32 dst = sb + mat*18432 + row*144 + s8*16;
        const hf* srcp =
            (mat==0) ? &qq[(size_t)(l0+row)*64 + s8*8]
                     : &kk[(size_t)(r0+row)*64 + s8*8];
        CP16(dst, srcp);
    }
    CP_COMMIT();
    load_de(0); CP_COMMIT();

    float acc[4][4][4];
#pragma unroll
    for (int i=0;i<4;i++)
#pragma unroll
        for (int j=0;j<4;j++)
#pragma unroll
            for (int c=0;c<4;c++) acc[i][j][c]=0.f;

    CP_WAIT(1);
    __syncthreads();

    // ---- phase 1: qk^T (x1) ----
#pragma unroll
    for (int kb=0;kb<64;kb+=16){
        u32 ah[4][4], bb[4][2];
#pragma unroll
        for (int mt=0;mt<4;mt++){
            u32 ra = sb + SC_Q + ((warpM*64+mt*16+lr)*72 + kb + lc8)*2;
            ldsm4(ah[mt][0],ah[mt][1],ah[mt][2],ah[mt][3], ra);
        }
#pragma unroll
        for (int gg=0;gg<2;gg++){
            u32 rb = sb + SC_K + ((warpN*32+gg*16+lr)*72 + kb + lc8)*2;
            u32 r0r,r1r,r2r,r3r;
            ldsm4(r0r,r1r,r2r,r3r, rb);
            bb[2*gg][0]=r0r; bb[2*gg][1]=r2r; bb[2*gg+1][0]=r1r; bb[2*gg+1][1]=r3r;
        }
#pragma unroll
        for (int mt=0;mt<4;mt++)
#pragma unroll
            for (int nt=0;nt<4;nt++)
                mma16816(acc[mt][nt], ah[mt], bb[nt][0], bb[nt][1]);
    }

    // ---- phase 2: pe via T = Q DE^T, 4 prefetched chunks; sT overlays K ----
    for (int c=0;c<4;c++){
        int t0c = 64*c;
        float Tacc[4][2][4];
#pragma unroll
        for (int i=0;i<4;i++)
#pragma unroll
            for (int j=0;j<2;j++)
#pragma unroll
                for (int q=0;q<4;q++) Tacc[i][j][q]=0.f;

        CP_WAIT(0);
        __syncthreads();
#pragma unroll
        for (int kb=0;kb<64;kb+=16){
            u32 ah[4][4];
#pragma unroll
            for (int mt=0;mt<4;mt++)
                ldsm4(ah[mt][0],ah[mt][1],ah[mt][2],ah[mt][3],
                      sb + SC_Q + ((warpM*64+mt*16+lr)*72 + kb + lc8)*2);
            u32 r0r,r1r,r2r,r3r;
            ldsm4(r0r,r1r,r2r,r3r, sb + SC_DE + ((warpN*16+lr)*72 + kb + lc8)*2);
#pragma unroll
            for (int mt=0;mt<4;mt++){
                mma16816(Tacc[mt][0], ah[mt], r0r, r2r);
                mma16816(Tacc[mt][1], ah[mt], r1r, r3r);
            }
        }
        __syncthreads();
        if (c < 3) { load_de(c+1); CP_COMMIT(); }

#pragma unroll
        for (int mt=0;mt<4;mt++)
#pragma unroll
            for (int n2=0;n2<2;n2++){
                int col = warpN*16 + n2*8 + 2*t;
                int rw = warpM*64 + mt*16 + g;
                *(float2*)&sT[rw*66 + col]     = make_float2(Tacc[mt][n2][0], Tacc[mt][n2][1]);
                *(float2*)&sT[(rw+8)*66 + col] = make_float2(Tacc[mt][n2][2], Tacc[mt][n2][3]);
            }
        __syncthreads();
#pragma unroll
        for (int mt=0;mt<4;mt++){
            int ib = warpM*64 + mt*16 + g;
#pragma unroll
            for (int nt=0;nt<4;nt++){
                int jb0 = warpN*32 + nt*8 + 2*t;
#pragma unroll
                for (int cr=0;cr<4;cr++){
                    int i = ib + (cr>>1)*8, j = jb0 + (cr&1);
                    int tt = i - j + 127 - t0c;
                    if ((unsigned)tt < 64u) acc[mt][nt][cr] += sT[i*66 + tt];
                }
            }
        }
        __syncthreads();
    }

    hf* outp = g_sc + (size_t)bh*SS*SS;
#pragma unroll
    for (int mt=0;mt<4;mt++){
        int i0 = l0 + warpM*64 + mt*16 + g;
#pragma unroll
        for (int nt=0;nt<4;nt++){
            int jc = r0 + warpN*32 + nt*8 + 2*t;
            float2 mk = *(const float2*)&mask[b_*SS + jc];
            *(u32*)&outp[(size_t)i0*SS + jc] =
                pack2h(fmaf(acc[mt][nt][0],0.125f,mk.x), fmaf(acc[mt][nt][1],0.125f,mk.y));
            *(u32*)&outp[(size_t)(i0+8)*SS + jc] =
                pack2h(fmaf(acc[mt][nt][2],0.125f,mk.x), fmaf(acc[mt][nt][3],0.125f,mk.y));
        }
    }
}

// ============================================================================
// K3: FUSED softmax + PV, 3 CTAs/SM (low-register variant).
// smem: P 32 x 1032 halves (66048B) | V 2 x 4608B (32 k-rows/stage).
// Phase A keeps only n[32] in regs; s re-read from smem each pass.
// Phase B: out(32x64) = P @ V, 32 stages of K=32, one barrier per stage.
// ============================================================================
#define FS_SMEM (66048 + 2*4608)
__device__ __forceinline__ float fast_neglog(float u)
{
    float up = u + 1e-10f;
    float d  = up - 1.0f;
    float p = d*(1.f + d*(-0.5f + d*(0.33333333f + d*(-0.25f + d*0.2f))));
    float lg = __logf(up);
    float l = (d > -0.03125f) ? p : lg;
    return 1e-10f - l;
}

__global__ __launch_bounds__(256, 3)
void softpv(const float* __restrict__ gum, float* __restrict__ out)
{
    extern __shared__ __align__(16) char smem[];
    hf* P = (hf*)smem;                     // 32 rows x 1032 halves
    const u32 sbP = sptr(smem);
    const u32 sbV = sbP + 66048;

    const int tid = threadIdx.x, wid = tid>>5, lane = tid&31;
    const int bh = blockIdx.y, l0 = blockIdx.x*32;
    const int b_ = bh>>4, h = bh&15;

    const hf* S = g_sc + (size_t)bh*SS*SS + (size_t)l0*SS;
    const hf* V = g_v + (size_t)bh*SS*HDD;

    auto load_v = [&](int st, int k0){
        int row = tid >> 3, s8 = tid & 7;   // 256 = 32 rows x 8 segs
        CP16(sbV + st*4608 + row*144 + s8*16, &V[(size_t)(k0+row)*64 + s8*8]);
    };

    // load scores 32x1024 (4096 x 16B transfers)
#pragma unroll
    for (int rep=0; rep<16; rep++){
        int idx = rep*256 + tid;
        int row = idx >> 7, c16 = idx & 127;
        CP16(sbP + row*2064 + c16*16, &S[(size_t)row*1024 + c16*8]);
    }
    CP_COMMIT();
    load_v(0, 0); CP_COMMIT();
    CP_WAIT(1);      // scores ready; V0 may still be in flight
    __syncthreads();

    // ---- phase A: double softmax, warp w owns rows w*4..w*4+3 ----
    for (int rr = 0; rr < 4; rr++) {
        int row = wid*4 + rr;
        const float* urow = gum + ((size_t)(bh*1024 + l0 + row))*1024;
        hf* prow = P + row*1032;

        float n[32];
        float m = -1e30f;
        // pass 1: row max + gumbel neglog
#pragma unroll
        for (int j = 0; j < 8; j++) {
            uint2 sv = *(const uint2*)&prow[j*128 + lane*4];
            float2 f0 = __half22float2(*(__half2*)&sv.x);
            float2 f1 = __half22float2(*(__half2*)&sv.y);
            m = fmaxf(m, fmaxf(fmaxf(f0.x, f0.y), fmaxf(f1.x, f1.y)));
            float4 u = *(const float4*)&urow[(j*32 + lane)*4];
            n[j*4+0] = fast_neglog(u.x);
            n[j*4+1] = fast_neglog(u.y);
            n[j*4+2] = fast_neglog(u.z);
            n[j*4+3] = fast_neglog(u.w);
        }
#pragma unroll
        for (int o = 16; o; o >>= 1) m = fmaxf(m, __shfl_xor_sync(0xffffffffu, m, o));

        // pass 2: n <- t/w, sum
        float sm1 = 0.f;
#pragma unroll
        for (int j = 0; j < 8; j++) {
            uint2 sv = *(const uint2*)&prow[j*128 + lane*4];
            float2 f0 = __half22float2(*(__half2*)&sv.x);
            float2 f1 = __half22float2(*(__half2*)&sv.y);
            float t0 = __expf(f0.x - m), t1 = __expf(f0.y - m);
            float t2 = __expf(f1.x - m), t3 = __expf(f1.y - m);
            n[j*4+0] = __fdividef(t0, n[j*4+0]);
            n[j*4+1] = __fdividef(t1, n[j*4+1]);
            n[j*4+2] = __fdividef(t2, n[j*4+2]);
            n[j*4+3] = __fdividef(t3, n[j*4+3]);
            sm1 += (n[j*4+0] + n[j*4+1]) + (n[j*4+2] + n[j*4+3]);
        }
#pragma unroll
        for (int o = 16; o; o >>= 1) sm1 += __shfl_xor_sync(0xffffffffu, sm1, o);
        float inv1 = __fdividef(1.0f, sm1);

        // pass 3: n <- p numerator, sum
        float sm2 = 0.f;
#pragma unroll
        for (int j = 0; j < 8; j++) {
            uint2 sv = *(const uint2*)&prow[j*128 + lane*4];
            float2 f0 = __half22float2(*(__half2*)&sv.x);
            float2 f1 = __half22float2(*(__half2*)&sv.y);
            float t0 = __expf(f0.x - m), t1 = __expf(f0.y - m);
            float t2 = __expf(f1.x - m), t3 = __expf(f1.y - m);
            n[j*4+0] = t0 * __expf(fmaf(n[j*4+0], inv1, -1.0f));
            n[j*4+1] = t1 * __expf(fmaf(n[j*4+1], inv1, -1.0f));
            n[j*4+2] = t2 * __expf(fmaf(n[j*4+2], inv1, -1.0f));
            n[j*4+3] = t3 * __expf(fmaf(n[j*4+3], inv1, -1.0f));
            sm2 += (n[j*4+0] + n[j*4+1]) + (n[j*4+2] + n[j*4+3]);
        }
#pragma unroll
        for (int o = 16; o; o >>= 1) sm2 += __shfl_xor_sync(0xffffffffu, sm2, o);
        float inv2 = __fdividef(1.0f, sm2);

        // pass 4: write p
#pragma unroll
        for (int j = 0; j < 8; j++) {
            float a = n[j*4+0]*inv2, b = n[j*4+1]*inv2;
            float c = n[j*4+2]*inv2, d = n[j*4+3]*inv2;
            *(uint2*)&prow[j*128 + lane*4] = make_uint2(pack2h(a,b), pack2h(c,d));
        }
    }
    __syncthreads();

    // ---- phase B: out(32x64) = P(32x1024) @ V(1024x64), 32 stages of K=32 ----
    const int warpM = wid>>2, warpN = wid&3;     // 2m x 4n, warp tile 16x16
    const int lr = lane&15, lc8 = (lane>>4)*8, g = lane>>2, t = lane&3;

    float acc[2][4];
#pragma unroll
    for (int i=0;i<2;i++)
#pragma unroll
        for (int c=0;c<4;c++) acc[i][c]=0.f;

    for (int c = 0; c < 32; c++) {
        CP_WAIT(0);          // stage c landed (issued one iteration ago)
        __syncthreads();     // also: everyone done reading stage c^1
        if (c < 31) { load_v((c+1)&1, (c+1)*32); CP_COMMIT(); }
        const u32 st = sbV + (c&1)*4608;
#pragma unroll
        for (int kb=0;kb<32;kb+=16){
            u32 ah[4];
            ldsm4(ah[0],ah[1],ah[2],ah[3],
                  sbP + (warpM*16+lr)*2064 + (c*32 + kb + lc8)*2);
            u32 r0,r1,r2,r3;
            ldsm4t(r0,r1,r2,r3, st + ((kb+lr)*72 + warpN*16 + lc8)*2);
            mma16816(acc[0], ah, r0, r1);
            mma16816(acc[1], ah, r2, r3);
        }
    }

#pragma unroll
    for (int nt=0; nt<2; nt++){
        int dcol = warpN*16 + nt*8 + 2*t;
#pragma unroll
        for (int rr=0; rr<2; rr++){
            int l = l0 + warpM*16 + g + rr*8;
            *(float2*)&out[((size_t)(b_*SS)+l)*1024 + h*64 + dcol] =
                make_float2(acc[nt][rr*2+0], acc[nt][rr*2+1]);
        }
    }
}

// ============================================================================
extern "C" void kernel_launch(void* const* d_in, const int* in_sizes, int n_in,
                              void* d_out, int out_size)
{
    const float* hidden = (const float*)d_in[0];
    const float* mask   = (const float*)d_in[1];
    const float* gum    = (const float*)d_in[2];
    const float* Wq     = (const float*)d_in[3];
    const float* bq     = (const float*)d_in[4];
    const float* Wk     = (const float*)d_in[5];
    const float* bk     = (const float*)d_in[6];
    const float* Wv     = (const float*)d_in[7];
    const float* bv     = (const float*)d_in[8];
    const float* de     = (const float*)d_in[9];
    float* out = (float*)d_out;

    static int configured = 0;
    if (!configured) {
        cudaFuncSetAttribute(qkv_mma,    cudaFuncAttributeMaxDynamicSharedMemorySize, QKV_SMEM);
        cudaFuncSetAttribute(scores_mma, cudaFuncAttributeMaxDynamicSharedMemorySize, SC_SMEM);
        cudaFuncSetAttribute(softpv,     cudaFuncAttributeMaxDynamicSharedMemorySize, FS_SMEM);
        configured = 1;
    }

    cvt_kernel<<<5249, 256>>>(hidden, Wq, Wk, Wv, de);
    qkv_mma<<<dim3(8, 16, 3), 256, QKV_SMEM>>>(bq, bk, bv);
    scores_mma<<<dim3(8, 8, 32), 256, SC_SMEM>>>(mask);
    softpv<<<dim3(32, 32), 256, FS_SMEM>>>(gum, out);
}

// round 17
// speedup vs baseline: 1.1324x; 1.1324x over previous
#include <cuda_runtime.h>
#include <cuda_fp16.h>
#include <math.h>

typedef unsigned int u32;
typedef __half hf;

#define SS 1024
#define HH 16
#define HDD 64
#define NBH 32

// ---------------- scratch (device globals) ----------------
__device__ hf g_x[2048*1024];
__device__ hf g_w[3*1024*1024];
__device__ hf g_de[2047*64];
__device__ hf g_q[NBH*SS*HDD];
__device__ hf g_k[NBH*SS*HDD];
__device__ hf g_v[NBH*SS*HDD];
__device__ hf g_sc[(size_t)NBH*SS*SS];

// ---------------- helpers ----------------
__device__ __forceinline__ u32 sptr(const void* p){ return (u32)__cvta_generic_to_shared(p); }
__device__ __forceinline__ void ldsm4(u32& r0,u32& r1,u32& r2,u32& r3,u32 a){
    asm volatile("ldmatrix.sync.aligned.m8n8.x4.shared.b16 {%0,%1,%2,%3},[%4];"
                 :"=r"(r0),"=r"(r1),"=r"(r2),"=r"(r3):"r"(a));
}
__device__ __forceinline__ void ldsm4t(u32& r0,u32& r1,u32& r2,u32& r3,u32 a){
    asm volatile("ldmatrix.sync.aligned.m8n8.x4.trans.shared.b16 {%0,%1,%2,%3},[%4];"
                 :"=r"(r0),"=r"(r1),"=r"(r2),"=r"(r3):"r"(a));
}
__device__ __forceinline__ void mma16816(float (&c)[4], const u32 (&a)[4], u32 b0, u32 b1){
    asm volatile("mma.sync.aligned.m16n8k16.row.col.f32.f16.f16.f32 "
                 "{%0,%1,%2,%3},{%4,%5,%6,%7},{%8,%9},{%0,%1,%2,%3};"
                 :"+f"(c[0]),"+f"(c[1]),"+f"(c[2]),"+f"(c[3])
                 :"r"(a[0]),"r"(a[1]),"r"(a[2]),"r"(a[3]),"r"(b0),"r"(b1));
}
__device__ __forceinline__ u32 pack2h(float a, float b){
    __half2 t; t.x=__float2half_rn(a); t.y=__float2half_rn(b);
    return *(u32*)&t;
}

#define CP16(dst, src) \
    asm volatile("cp.async.cg.shared.global [%0], [%1], 16;" :: "r"(dst), "l"(src))
#define CP_COMMIT() asm volatile("cp.async.commit_group;" ::: "memory")
#define CP_WAIT(n)  asm volatile("cp.async.wait_group %0;" :: "n"(n) : "memory")

// ============================================================================
// K0: fp32 -> fp16 (single rounding) for X, W, de.
// ============================================================================
__global__ __launch_bounds__(256)
void cvt_kernel(const float* __restrict__ X, const float* __restrict__ Wq,
                const float* __restrict__ Wk, const float* __restrict__ Wv,
                const float* __restrict__ de)
{
    int i = blockIdx.x * 256 + threadIdx.x;
    if (i >= 1343472) return;
    const float* src; hf* dst; int off;
    if (i < 524288) {
        src = X; dst = g_x; off = i;
    } else if (i < 1310720) {
        off = i - 524288;
        int wsel = off >> 18;
        src = (wsel==0)?Wq:(wsel==1)?Wk:Wv;
        dst = g_w + (size_t)wsel * 1048576;
        off &= 262143;
    } else {
        off = i - 1310720; src = de; dst = g_de;
    }
    float4 v = *(const float4*)(src + (size_t)off * 4);
    *(uint2*)(dst + (size_t)off*4) = make_uint2(pack2h(v.x,v.y), pack2h(v.z,v.w));
}

// ============================================================================
// K1: q/k/v = X @ W^T + b (fp16 x1). CTA 128x128, BK=64, cp.async 2-stage,
// 2 CTAs/SM.
// ============================================================================
#define QKV_SMEM (2*36864)
__global__ __launch_bounds__(256, 2)
void qkv_mma(const float* __restrict__ bq, const float* __restrict__ bk,
             const float* __restrict__ bv)
{
    extern __shared__ __align__(16) char smem[];
    const u32 sb = sptr(smem);

    const int tid = threadIdx.x, wid = tid>>5, lane = tid&31;
    const int warpM = wid>>2, warpN = wid&3;
    const int z = blockIdx.z, n0 = blockIdx.x*128, m0 = blockIdx.y*128;
    const int lr = lane&15, lc8 = (lane>>4)*8, g = lane>>2, t = lane&3;

    const hf* B = g_w + (size_t)z*1048576;
    const float* bias = (z==0)?bq:(z==1)?bk:bv;
    hf* dq = (z==0)?g_q:(z==1)?g_k:g_v;

    float acc[4][4][4];
#pragma unroll
    for (int i=0;i<4;i++)
#pragma unroll
        for (int j=0;j<4;j++)
#pragma unroll
            for (int c=0;c<4;c++) acc[i][j][c]=0.f;

    auto load_stage = [&](int st, int k0){
        const u32 base = sb + st*36864;
#pragma unroll
        for (int rep=0;rep<8;rep++){
            int idx = rep*256 + tid;
            int mat = idx >> 10, rem = idx & 1023;
            int row = rem >> 3, s8 = rem & 7;
            u32 dst = base + mat*18432 + row*144 + s8*16;
            const hf* srcp =
                (mat==0) ? &g_x[(size_t)(m0+row)*1024 + k0 + s8*8]
                         : &B[(size_t)(n0+row)*1024 + k0 + s8*8];
            CP16(dst, srcp);
        }
    };

    load_stage(0, 0); CP_COMMIT();

    for (int c = 0; c < 16; c++) {
        if (c < 15) { load_stage((c+1)&1, (c+1)*64); CP_COMMIT(); CP_WAIT(1); }
        else        { CP_WAIT(0); }
        __syncthreads();
        const u32 st = sb + (c&1)*36864;
#pragma unroll
        for (int kb=0;kb<64;kb+=16){
            u32 ah[4][4], bb[4][2];
#pragma unroll
            for (int mt=0;mt<4;mt++){
                u32 ra = st + ((warpM*64+mt*16+lr)*72 + kb + lc8)*2;
                ldsm4(ah[mt][0],ah[mt][1],ah[mt][2],ah[mt][3], ra);
            }
#pragma unroll
            for (int gg=0;gg<2;gg++){
                u32 rb = st + 18432 + ((warpN*32+gg*16+lr)*72 + kb + lc8)*2;
                u32 r0,r1,r2,r3;
                ldsm4(r0,r1,r2,r3, rb);
                bb[2*gg][0]=r0; bb[2*gg][1]=r2; bb[2*gg+1][0]=r1; bb[2*gg+1][1]=r3;
            }
#pragma unroll
            for (int mt=0;mt<4;mt++)
#pragma unroll
                for (int nt=0;nt<4;nt++)
                    mma16816(acc[mt][nt], ah[mt], bb[nt][0], bb[nt][1]);
        }
        __syncthreads();
    }

#pragma unroll
    for (int mt=0;mt<4;mt++)
#pragma unroll
        for (int nt=0;nt<4;nt++){
            int ncol = n0 + warpN*32 + nt*8 + 2*t;
            float b0 = bias[ncol], b1 = bias[ncol+1];
            int h = ncol>>6, dd = ncol&63;
#pragma unroll
            for (int rr=0;rr<2;rr++){
                int m = m0 + warpM*64 + mt*16 + g + rr*8;
                int b_ = m>>10, l = m&1023;
                float v0 = acc[mt][nt][rr*2+0] + b0;
                float v1 = acc[mt][nt][rr*2+1] + b1;
                size_t o = (((size_t)(b_*HH + h))*SS + l)*HDD + dd;
                *(u32*)&dq[o] = pack2h(v0, v1);
            }
        }
}

// ============================================================================
// K2: scores = (q k^T)[fp16 x1] + Toeplitz(Q DE^T)[x1], *0.125 + mask -> fp16
// ============================================================================
#define SC_SMEM 61440
#define SC_Q  0
#define SC_K  18432
#define SC_T  18432
#define SC_DE 52224
__global__ __launch_bounds__(256, 2)
void scores_mma(const float* __restrict__ mask)
{
    extern __shared__ __align__(16) char smem[];
    const u32 sb = sptr(smem);
    float* sT = (float*)(smem + SC_T);

    const int tid = threadIdx.x, wid = tid>>5, lane = tid&31;
    const int warpM = wid>>2, warpN = wid&3;
    const int bh = blockIdx.z, l0 = blockIdx.y*128, r0 = blockIdx.x*128;
    const int b_ = bh>>4;
    const int jb = l0 - r0 + 896;
    const int lr = lane&15, lc8 = (lane>>4)*8, g = lane>>2, t = lane&3;

    const hf* qq = g_q + (size_t)bh*SS*HDD;
    const hf* kk = g_k + (size_t)bh*SS*HDD;

    auto load_de = [&](int cchunk){
#pragma unroll
        for (int rep=0;rep<2;rep++){
            int idx = rep*256 + tid;
            int row = idx >> 3, s8 = idx & 7;
            int der = jb + cchunk*64 + row; if (der > 2046) der = 2046;
            CP16(sb + SC_DE + row*144 + s8*16, &g_de[(size_t)der*64 + s8*8]);
        }
    };

#pragma unroll
    for (int rep=0;rep<8;rep++){
        int idx = rep*256 + tid;
        int mat = idx >> 10, rem = idx & 1023;
        int row = rem >> 3, s8 = rem & 7;
        u32 dst = sb + mat*18432 + row*144 + s8*16;
        const hf* srcp =
            (mat==0) ? &qq[(size_t)(l0+row)*64 + s8*8]
                     : &kk[(size_t)(r0+row)*64 + s8*8];
        CP16(dst, srcp);
    }
    CP_COMMIT();
    load_de(0); CP_COMMIT();

    float acc[4][4][4];
#pragma unroll
    for (int i=0;i<4;i++)
#pragma unroll
        for (int j=0;j<4;j++)
#pragma unroll
            for (int c=0;c<4;c++) acc[i][j][c]=0.f;

    CP_WAIT(1);
    __syncthreads();

    // ---- phase 1: qk^T (x1) ----
#pragma unroll
    for (int kb=0;kb<64;kb+=16){
        u32 ah[4][4], bb[4][2];
#pragma unroll
        for (int mt=0;mt<4;mt++){
            u32 ra = sb + SC_Q + ((warpM*64+mt*16+lr)*72 + kb + lc8)*2;
            ldsm4(ah[mt][0],ah[mt][1],ah[mt][2],ah[mt][3], ra);
        }
#pragma unroll
        for (int gg=0;gg<2;gg++){
            u32 rb = sb + SC_K + ((warpN*32+gg*16+lr)*72 + kb + lc8)*2;
            u32 r0r,r1r,r2r,r3r;
            ldsm4(r0r,r1r,r2r,r3r, rb);
            bb[2*gg][0]=r0r; bb[2*gg][1]=r2r; bb[2*gg+1][0]=r1r; bb[2*gg+1][1]=r3r;
        }
#pragma unroll
        for (int mt=0;mt<4;mt++)
#pragma unroll
            for (int nt=0;nt<4;nt++)
                mma16816(acc[mt][nt], ah[mt], bb[nt][0], bb[nt][1]);
    }

    // ---- phase 2: pe via T = Q DE^T, 4 prefetched chunks; sT overlays K ----
    for (int c=0;c<4;c++){
        int t0c = 64*c;
        float Tacc[4][2][4];
#pragma unroll
        for (int i=0;i<4;i++)
#pragma unroll
            for (int j=0;j<2;j++)
#pragma unroll
                for (int q=0;q<4;q++) Tacc[i][j][q]=0.f;

        CP_WAIT(0);
        __syncthreads();
#pragma unroll
        for (int kb=0;kb<64;kb+=16){
            u32 ah[4][4];
#pragma unroll
            for (int mt=0;mt<4;mt++)
                ldsm4(ah[mt][0],ah[mt][1],ah[mt][2],ah[mt][3],
                      sb + SC_Q + ((warpM*64+mt*16+lr)*72 + kb + lc8)*2);
            u32 r0r,r1r,r2r,r3r;
            ldsm4(r0r,r1r,r2r,r3r, sb + SC_DE + ((warpN*16+lr)*72 + kb + lc8)*2);
#pragma unroll
            for (int mt=0;mt<4;mt++){
                mma16816(Tacc[mt][0], ah[mt], r0r, r2r);
                mma16816(Tacc[mt][1], ah[mt], r1r, r3r);
            }
        }
        __syncthreads();
        if (c < 3) { load_de(c+1); CP_COMMIT(); }

#pragma unroll
        for (int mt=0;mt<4;mt++)
#pragma unroll
            for (int n2=0;n2<2;n2++){
                int col = warpN*16 + n2*8 + 2*t;
                int rw = warpM*64 + mt*16 + g;
                *(float2*)&sT[rw*66 + col]     = make_float2(Tacc[mt][n2][0], Tacc[mt][n2][1]);
                *(float2*)&sT[(rw+8)*66 + col] = make_float2(Tacc[mt][n2][2], Tacc[mt][n2][3]);
            }
        __syncthreads();
#pragma unroll
        for (int mt=0;mt<4;mt++){
            int ib = warpM*64 + mt*16 + g;
#pragma unroll
            for (int nt=0;nt<4;nt++){
                int jb0 = warpN*32 + nt*8 + 2*t;
#pragma unroll
                for (int cr=0;cr<4;cr++){
                    int i = ib + (cr>>1)*8, j = jb0 + (cr&1);
                    int tt = i - j + 127 - t0c;
                    if ((unsigned)tt < 64u) acc[mt][nt][cr] += sT[i*66 + tt];
                }
            }
        }
        __syncthreads();
    }

    hf* outp = g_sc + (size_t)bh*SS*SS;
#pragma unroll
    for (int mt=0;mt<4;mt++){
        int i0 = l0 + warpM*64 + mt*16 + g;
#pragma unroll
        for (int nt=0;nt<4;nt++){
            int jc = r0 + warpN*32 + nt*8 + 2*t;
            float2 mk = *(const float2*)&mask[b_*SS + jc];
            *(u32*)&outp[(size_t)i0*SS + jc] =
                pack2h(fmaf(acc[mt][nt][0],0.125f,mk.x), fmaf(acc[mt][nt][1],0.125f,mk.y));
            *(u32*)&outp[(size_t)(i0+8)*SS + jc] =
                pack2h(fmaf(acc[mt][nt][2],0.125f,mk.x), fmaf(acc[mt][nt][3],0.125f,mk.y));
        }
    }
}

// ============================================================================
// K3: FUSED softmax + PV (R14 structure restored). 2 CTAs/SM.
// smem: P 32 x 1032 halves (66048B) | V 2 x 18432B (128 k-rows/stage).
// Phase A: registers s[32]+n[32], single smem read pass.
// Phase B: out = P @ V, 8 stages of K=128.
// A->B transition uses half-CTA named barriers (group g reads only its rows).
// ============================================================================
#define FS_SMEM (66048 + 2*18432)
__device__ __forceinline__ float fast_neglog(float u)
{
    float up = u + 1e-10f;
    float d  = up - 1.0f;
    float p = d*(1.f + d*(-0.5f + d*(0.33333333f + d*(-0.25f + d*0.2f))));
    float lg = __logf(up);
    float l = (d > -0.03125f) ? p : lg;
    return 1e-10f - l;
}

__global__ __launch_bounds__(256, 2)
void softpv(const float* __restrict__ gum, float* __restrict__ out)
{
    extern __shared__ __align__(16) char smem[];
    hf* P = (hf*)smem;                     // 32 rows x 1032 halves
    const u32 sbP = sptr(smem);
    const u32 sbV = sbP + 66048;

    const int tid = threadIdx.x, wid = tid>>5, lane = tid&31;
    const int bh = blockIdx.y, l0 = blockIdx.x*32;
    const int b_ = bh>>4, h = bh&15;

    const hf* S = g_sc + (size_t)bh*SS*SS + (size_t)l0*SS;
    const hf* V = g_v + (size_t)bh*SS*HDD;

    auto load_v = [&](int st, int k0){
#pragma unroll
        for (int rep=0;rep<4;rep++){
            int idx = rep*256 + tid;
            int row = idx >> 3, s8 = idx & 7;
            CP16(sbV + st*18432 + row*144 + s8*16, &V[(size_t)(k0+row)*64 + s8*8]);
        }
    };

    // load scores 32x1024 (4096 x 16B transfers)
#pragma unroll
    for (int rep=0; rep<16; rep++){
        int idx = rep*256 + tid;
        int row = idx >> 7, c16 = idx & 127;
        CP16(sbP + row*2064 + c16*16, &S[(size_t)row*1024 + c16*8]);
    }
    CP_COMMIT();
    load_v(0, 0); CP_COMMIT();
    CP_WAIT(0);
    __syncthreads();

    // ---- phase A: double softmax, warp w owns rows w*4..w*4+3 ----
    for (int rr = 0; rr < 4; rr++) {
        int row = wid*4 + rr;
        const float* urow = gum + ((size_t)(bh*1024 + l0 + row))*1024;
        hf* prow = P + row*1032;

        float s[32], n[32];
#pragma unroll
        for (int j = 0; j < 8; j++) {
            uint2 sv = *(const uint2*)&prow[j*128 + lane*4];
            float2 f0 = __half22float2(*(__half2*)&sv.x);
            float2 f1 = __half22float2(*(__half2*)&sv.y);
            s[j*4+0]=f0.x; s[j*4+1]=f0.y; s[j*4+2]=f1.x; s[j*4+3]=f1.y;
            float4 u = *(const float4*)&urow[(j*32 + lane)*4];
            n[j*4+0] = fast_neglog(u.x);
            n[j*4+1] = fast_neglog(u.y);
            n[j*4+2] = fast_neglog(u.z);
            n[j*4+3] = fast_neglog(u.w);
        }
        float m = s[0];
#pragma unroll
        for (int i = 1; i < 32; i++) m = fmaxf(m, s[i]);
#pragma unroll
        for (int o = 16; o; o >>= 1) m = fmaxf(m, __shfl_xor_sync(0xffffffffu, m, o));

        float sm1 = 0.f;
#pragma unroll
        for (int i = 0; i < 32; i++) {
            s[i] = __expf(s[i] - m);
            n[i] = __fdividef(s[i], n[i]);
            sm1 += n[i];
        }
#pragma unroll
        for (int o = 16; o; o >>= 1) sm1 += __shfl_xor_sync(0xffffffffu, sm1, o);
        float inv1 = __fdividef(1.0f, sm1);

        float sm2 = 0.f;
#pragma unroll
        for (int i = 0; i < 32; i++) {
            n[i] = s[i] * __expf(fmaf(n[i], inv1, -1.0f));
            sm2 += n[i];
        }
#pragma unroll
        for (int o = 16; o; o >>= 1) sm2 += __shfl_xor_sync(0xffffffffu, sm2, o);
        float inv2 = __fdividef(1.0f, sm2);

#pragma unroll
        for (int j = 0; j < 8; j++) {
            float a = n[j*4+0]*inv2, b = n[j*4+1]*inv2;
            float c = n[j*4+2]*inv2, d = n[j*4+3]*inv2;
            *(uint2*)&prow[j*128 + lane*4] = make_uint2(pack2h(a,b), pack2h(c,d));
        }
    }
    // half-CTA transition: warps 0-3 (P rows 0-15) / warps 4-7 (rows 16-31)
    if (wid < 4) asm volatile("bar.sync 1, 128;" ::: "memory");
    else         asm volatile("bar.sync 2, 128;" ::: "memory");

    // ---- phase B: out(32x64) = P(32x1024) @ V(1024x64) ----
    const int warpM = wid>>2, warpN = wid&3;     // 2m x 4n, warp tile 16x16
    const int lr = lane&15, lc8 = (lane>>4)*8, g = lane>>2, t = lane&3;

    float acc[2][4];
#pragma unroll
    for (int i=0;i<2;i++)
#pragma unroll
        for (int c=0;c<4;c++) acc[i][c]=0.f;

    for (int c = 0; c < 8; c++) {
        if (c < 7) { load_v((c+1)&1, (c+1)*128); CP_COMMIT(); CP_WAIT(1); }
        else       { CP_WAIT(0); }
        __syncthreads();
        const u32 st = sbV + (c&1)*18432;
#pragma unroll
        for (int kb=0;kb<128;kb+=16){
            u32 ah[4];
            ldsm4(ah[0],ah[1],ah[2],ah[3],
                  sbP + (warpM*16+lr)*2064 + (c*128 + kb + lc8)*2);
            u32 r0,r1,r2,r3;
            ldsm4t(r0,r1,r2,r3, st + ((kb+lr)*72 + warpN*16 + lc8)*2);
            mma16816(acc[0], ah, r0, r1);
            mma16816(acc[1], ah, r2, r3);
        }
        __syncthreads();   // all reads of stage c done before it is overwritten
    }

#pragma unroll
    for (int nt=0; nt<2; nt++){
        int dcol = warpN*16 + nt*8 + 2*t;
#pragma unroll
        for (int rr=0; rr<2; rr++){
            int l = l0 + warpM*16 + g + rr*8;
            *(float2*)&out[((size_t)(b_*SS)+l)*1024 + h*64 + dcol] =
                make_float2(acc[nt][rr*2+0], acc[nt][rr*2+1]);
        }
    }
}

// ============================================================================
extern "C" void kernel_launch(void* const* d_in, const int* in_sizes, int n_in,
                              void* d_out, int out_size)
{
    const float* hidden = (const float*)d_in[0];
    const float* mask   = (const float*)d_in[1];
    const float* gum    = (const float*)d_in[2];
    const float* Wq     = (const float*)d_in[3];
    const float* bq     = (const float*)d_in[4];
    const float* Wk     = (const float*)d_in[5];
    const float* bk     = (const float*)d_in[6];
    const float* Wv     = (const float*)d_in[7];
    const float* bv     = (const float*)d_in[8];
    const float* de     = (const float*)d_in[9];
    float* out = (float*)d_out;

    static int configured = 0;
    if (!configured) {
        cudaFuncSetAttribute(qkv_mma,    cudaFuncAttributeMaxDynamicSharedMemorySize, QKV_SMEM);
        cudaFuncSetAttribute(scores_mma, cudaFuncAttributeMaxDynamicSharedMemorySize, SC_SMEM);
        cudaFuncSetAttribute(softpv,     cudaFuncAttributeMaxDynamicSharedMemorySize, FS_SMEM);
        configured = 1;
    }

    cvt_kernel<<<5249, 256>>>(hidden, Wq, Wk, Wv, de);
    qkv_mma<<<dim3(8, 16, 3), 256, QKV_SMEM>>>(bq, bk, bv);
    scores_mma<<<dim3(8, 8, 32), 256, SC_SMEM>>>(mask);
    softpv<<<dim3(32, 32), 256, FS_SMEM>>>(gum, out);
}